// round 1
// baseline (speedup 1.0000x reference)
#include <cuda_runtime.h>
#include <math.h>

#define EDIM   512
#define TSTEPS 8
#define NWIN   8192                    // B(16) * nw(512)
#define XROWS  (NWIN * TSTEPS)         // 65536

// Scratch: precomputed input projection and H ping-pong buffers.
__device__ float g_pre[(size_t)XROWS * EDIM];        // 134 MB
__device__ float g_h[2][(size_t)NWIN * EDIM];        // 2 x 16.8 MB

// ---------------------------------------------------------------------------
// SGEMM: C[m][n] = sum_k A[m][k] * W[n][k]   (+ epilogue)
//   mode 0: C = acc + b0[n] + b1[n]                      (input projection)
//   mode 1: C = tanh(acc + g_pre[(m*8 + t)][n])          (recurrent step)
// Tiles: BM=128, BN=128, BK=8; 256 threads; 8x8 per thread.
// grid.x = N/128 (=4), grid.y = M/128.
// ---------------------------------------------------------------------------
__global__ __launch_bounds__(256, 2)
void sgemm_rnn(const float* __restrict__ A,
               const float* __restrict__ W,
               float* __restrict__ C,
               const float* __restrict__ b0,
               const float* __restrict__ b1,
               int mode, int t)
{
    __shared__ float As[8][128];
    __shared__ float Bs[8][128];

    const int bm = blockIdx.y * 128;
    const int bn = blockIdx.x * 128;
    const int tid = threadIdx.x;
    const int tr = tid >> 4;          // 0..15  (m group)
    const int tc = tid & 15;          // 0..15  (n group)

    // Loader mapping: 256 threads, each loads one float4 of A and one of B.
    const int ld_row = tid >> 1;       // 0..127
    const int ld_k4  = (tid & 1) * 4;  // 0 or 4

    float acc[8][8];
    #pragma unroll
    for (int i = 0; i < 8; i++)
        #pragma unroll
        for (int j = 0; j < 8; j++) acc[i][j] = 0.0f;

    const float* Arow = A + (size_t)(bm + ld_row) * EDIM + ld_k4;
    const float* Wrow = W + (size_t)(bn + ld_row) * EDIM + ld_k4;

    for (int k0 = 0; k0 < EDIM; k0 += 8) {
        float4 av = *(const float4*)(Arow + k0);
        float4 bv = *(const float4*)(Wrow + k0);
        As[ld_k4 + 0][ld_row] = av.x;
        As[ld_k4 + 1][ld_row] = av.y;
        As[ld_k4 + 2][ld_row] = av.z;
        As[ld_k4 + 3][ld_row] = av.w;
        Bs[ld_k4 + 0][ld_row] = bv.x;
        Bs[ld_k4 + 1][ld_row] = bv.y;
        Bs[ld_k4 + 2][ld_row] = bv.z;
        Bs[ld_k4 + 3][ld_row] = bv.w;
        __syncthreads();

        #pragma unroll
        for (int k = 0; k < 8; k++) {
            float4 a0 = *(const float4*)&As[k][tr * 8];
            float4 a1 = *(const float4*)&As[k][tr * 8 + 4];
            float4 c0 = *(const float4*)&Bs[k][tc * 8];
            float4 c1 = *(const float4*)&Bs[k][tc * 8 + 4];
            float a[8] = {a0.x, a0.y, a0.z, a0.w, a1.x, a1.y, a1.z, a1.w};
            float b[8] = {c0.x, c0.y, c0.z, c0.w, c1.x, c1.y, c1.z, c1.w};
            #pragma unroll
            for (int i = 0; i < 8; i++)
                #pragma unroll
                for (int j = 0; j < 8; j++)
                    acc[i][j] = fmaf(a[i], b[j], acc[i][j]);
        }
        __syncthreads();
    }

    const int nbase = bn + tc * 8;
    if (mode == 0) {
        float bias[8];
        #pragma unroll
        for (int j = 0; j < 8; j++) bias[j] = b0[nbase + j] + b1[nbase + j];
        #pragma unroll
        for (int i = 0; i < 8; i++) {
            size_t row = (size_t)(bm + tr * 8 + i);
            float* crow = C + row * EDIM + nbase;
            #pragma unroll
            for (int j = 0; j < 8; j++) crow[j] = acc[i][j] + bias[j];
        }
    } else {
        #pragma unroll
        for (int i = 0; i < 8; i++) {
            size_t m = (size_t)(bm + tr * 8 + i);
            const float* prow = g_pre + (m * TSTEPS + t) * (size_t)EDIM + nbase;
            float* crow = C + m * EDIM + nbase;
            #pragma unroll
            for (int j = 0; j < 8; j++)
                crow[j] = tanhf(acc[i][j] + prow[j]);
        }
    }
}

// H0 = tanh(pre at t=0)  (h_{-1} = 0 so no matmul for the first step)
__global__ __launch_bounds__(256)
void h0_kernel()
{
    size_t i = (size_t)blockIdx.x * 256 + threadIdx.x;   // 0 .. NWIN*EDIM-1
    int e = (int)(i & (EDIM - 1));
    size_t n = i >> 9;
    g_h[0][i] = tanhf(g_pre[(n * TSTEPS) * (size_t)EDIM + e]);
}

extern "C" void kernel_launch(void* const* d_in, const int* in_sizes, int n_in,
                              void* d_out, int out_size)
{
    (void)in_sizes; (void)n_in; (void)out_size;
    const float* x    = (const float*)d_in[0];   // [16,4096,512] == [65536,512]
    const float* W_ih = (const float*)d_in[1];   // [512,512]
    const float* W_hh = (const float*)d_in[2];   // [512,512]
    const float* b_ih = (const float*)d_in[3];   // [512]
    const float* b_hh = (const float*)d_in[4];   // [512]
    float* out = (float*)d_out;                  // [16,512,512] == [8192,512]

    static float* p_pre = nullptr;
    static float* p_h[2] = {nullptr, nullptr};
    if (!p_pre) {
        void* p;
        cudaGetSymbolAddress(&p, g_pre);
        p_pre = (float*)p;
        cudaGetSymbolAddress(&p, g_h);
        p_h[0] = (float*)p;
        p_h[1] = p_h[0] + (size_t)NWIN * EDIM;
    }

    // 1) PRE = X @ W_ih^T + (b_ih + b_hh)  : M=65536
    sgemm_rnn<<<dim3(4, 512), 256>>>(x, W_ih, p_pre, b_ih, b_hh, 0, 0);

    // 2) H0 = tanh(PRE_t0)
    h0_kernel<<<(NWIN * EDIM) / 256, 256>>>();

    // 3) H_t = tanh(PRE_t + H_{t-1} @ W_hh^T), t = 1..7 ; t=7 writes d_out.
    for (int t = 1; t < TSTEPS; t++) {
        float* src = p_h[(t - 1) & 1];
        float* dst = (t == TSTEPS - 1) ? out : p_h[t & 1];
        sgemm_rnn<<<dim3(4, 64), 256>>>(src, W_hh, dst, nullptr, nullptr, 1, t);
    }
}

// round 3
// speedup vs baseline: 2.1327x; 2.1327x over previous
#include <cuda_runtime.h>
#include <cuda_bf16.h>
#include <cstdint>
#include <math.h>

#define EDIM   512
#define TSTEPS 8
#define NWIN   8192
#define XROWS  65536
#define KSPLIT 1536            // 3 * EDIM  (bf16x3 split concatenated on K)
#define BK     32              // bf16 K per smem tile
#define NKIT   (KSPLIT / BK)   // 48
#define ROWB   80              // padded smem row stride in bytes (64B data + 16B pad)
#define TILEB  (128 * ROWB)    // 10240 B per operand tile
#define BUFB   (2 * TILEB)     // A+B for one buffer

// ---------------- scratch (device globals; no runtime allocation) ----------
__device__ __nv_bfloat16 g_xs[(size_t)XROWS * KSPLIT];      // 201 MB
__device__ __nv_bfloat16 g_ws[2][(size_t)EDIM * KSPLIT];    // 2 x 1.5 MB
__device__ __nv_bfloat16 g_hs[2][(size_t)NWIN * KSPLIT];    // 2 x 25 MB
__device__ float         g_pre[(size_t)XROWS * EDIM];       // 134 MB

// ---------------- helpers ----------------------------------------------------
__device__ __forceinline__ uint32_t smem_u32(const void* p) {
    uint32_t a;
    asm("{ .reg .u64 t; cvta.to.shared.u64 t, %1; cvt.u32.u64 %0, t; }"
        : "=r"(a) : "l"(p));
    return a;
}
__device__ __forceinline__ void cp16(uint32_t saddr, const void* gaddr) {
    asm volatile("cp.async.cg.shared.global [%0], [%1], 16;"
                 :: "r"(saddr), "l"(gaddr) : "memory");
}
__device__ __forceinline__ void cp_commit() {
    asm volatile("cp.async.commit_group;" ::: "memory");
}
template <int N>
__device__ __forceinline__ void cp_wait() {
    asm volatile("cp.async.wait_group %0;" :: "n"(N) : "memory");
}
__device__ __forceinline__ void ldsm4(uint32_t& r0, uint32_t& r1, uint32_t& r2,
                                      uint32_t& r3, uint32_t addr) {
    asm volatile("ldmatrix.sync.aligned.m8n8.x4.shared.b16 {%0,%1,%2,%3}, [%4];"
                 : "=r"(r0), "=r"(r1), "=r"(r2), "=r"(r3) : "r"(addr));
}
__device__ __forceinline__ void mma16816(float* c, const uint32_t* a,
                                         uint32_t b0, uint32_t b1) {
    asm volatile("mma.sync.aligned.m16n8k16.row.col.f32.bf16.bf16.f32 "
                 "{%0,%1,%2,%3}, {%4,%5,%6,%7}, {%8,%9}, {%0,%1,%2,%3};"
                 : "+f"(c[0]), "+f"(c[1]), "+f"(c[2]), "+f"(c[3])
                 : "r"(a[0]), "r"(a[1]), "r"(a[2]), "r"(a[3]), "r"(b0), "r"(b1));
}
__device__ __forceinline__ void split2(float v, __nv_bfloat16& hi, __nv_bfloat16& lo) {
    hi = __float2bfloat16(v);
    lo = __float2bfloat16(v - __bfloat162float(hi));
}

// ---------------- prep kernels ----------------------------------------------
__global__ __launch_bounds__(256)
void prep_w(const float* __restrict__ wih, const float* __restrict__ whh) {
    int idx = blockIdx.x * 256 + threadIdx.x;           // 0 .. 2*512*512-1
    int which = idx >> 18;
    int e = idx & 262143;
    int n = e >> 9, k = e & 511;
    const float* src = which ? whh : wih;
    __nv_bfloat16 hi, lo;
    split2(src[n * 512 + k], hi, lo);
    __nv_bfloat16* dst = g_ws[which] + (size_t)n * KSPLIT;
    dst[k] = hi; dst[512 + k] = lo; dst[1024 + k] = hi;
}

__global__ __launch_bounds__(256)
void prep_x(const float* __restrict__ x) {
    size_t idx = (size_t)blockIdx.x * 256 + threadIdx.x;  // over 65536*128 float4
    size_t row = idx >> 7;
    int q = (int)(idx & 127);
    float4 v = ((const float4*)x)[idx];
    __nv_bfloat16 h0,h1,h2,h3,l0,l1,l2,l3;
    split2(v.x,h0,l0); split2(v.y,h1,l1); split2(v.z,h2,l2); split2(v.w,h3,l3);
    __nv_bfloat16* base = g_xs + row * KSPLIT + q * 4;
    *(__nv_bfloat162*)(base)        = __nv_bfloat162{h0,h1};
    *(__nv_bfloat162*)(base + 2)    = __nv_bfloat162{h2,h3};
    *(__nv_bfloat162*)(base + 512)  = __nv_bfloat162{h0,h1};
    *(__nv_bfloat162*)(base + 514)  = __nv_bfloat162{h2,h3};
    *(__nv_bfloat162*)(base + 1024) = __nv_bfloat162{l0,l1};
    *(__nv_bfloat162*)(base + 1026) = __nv_bfloat162{l2,l3};
}

// ---------------- bf16x3 HMMA GEMM ------------------------------------------
// C[m][n] = sum_k A''[m][k] * W''[n][k]   (K'' = 1536 bf16, fp32 accum)
// mode 0: g_pre[m][n] = acc + bias[n]; rows with m%8==0 also write tanh-split H0
// mode 1: h = tanh(acc + g_pre[m*8+t][n]); split-bf16 h out (or fp32 out at t=7)
__global__ __launch_bounds__(256, 2)
void gemm_bf16x3(const __nv_bfloat16* __restrict__ A,
                 const __nv_bfloat16* __restrict__ Bw,
                 const float* __restrict__ b0, const float* __restrict__ b1,
                 float* __restrict__ outp, __nv_bfloat16* __restrict__ hs_out,
                 __nv_bfloat16* __restrict__ h0_out,
                 int mode, int t)
{
    extern __shared__ __align__(16) char dyn[];   // [2][A:10240 | B:10240]
    __shared__ float s_bias[128];

    const int tid = threadIdx.x;
    const int wid = tid >> 5;
    const int lane = tid & 31;
    const int warpM = wid & 3;           // 4 warps along M
    const int warpN = wid >> 2;          // 2 warps along N
    const int bm = blockIdx.y * 128;
    const int bn = blockIdx.x * 128;

    const uint32_t sbase = smem_u32(dyn);

    if (mode == 0 && tid < 128) s_bias[tid] = b0[bn + tid] + b1[bn + tid];

    // Loader mapping: 512 16B-chunks per operand tile; thread does 2 (A) + 2 (B).
    const int l_row0 = tid >> 2;            // rows 0..63
    const int l_row1 = l_row0 + 64;         // rows 64..127
    const int l_ch   = tid & 3;             // 16B chunk 0..3
    const uint4* A4 = (const uint4*)A;      // global row stride = 192 uint4
    const uint4* B4 = (const uint4*)Bw;

    const uint32_t sA0 = l_row0 * ROWB + l_ch * 16;
    const uint32_t sA1 = l_row1 * ROWB + l_ch * 16;

    // ldmatrix lane address offsets (constant across k iterations).
    const int g = lane >> 3;
    uint32_t a_off[2], b_off[4];
    #pragma unroll
    for (int mt = 0; mt < 2; mt++)
        a_off[mt] = (uint32_t)((warpM * 32 + mt * 16 + (g & 1) * 8 + (lane & 7)) * ROWB
                               + (g >> 1) * 16);
    #pragma unroll
    for (int np = 0; np < 4; np++)
        b_off[np] = (uint32_t)((warpN * 64 + np * 16 + (g >> 1) * 8 + (lane & 7)) * ROWB
                               + (g & 1) * 16);

    float acc[2][8][4];
    #pragma unroll
    for (int i = 0; i < 2; i++)
        #pragma unroll
        for (int j = 0; j < 8; j++)
            #pragma unroll
            for (int q = 0; q < 4; q++) acc[i][j][q] = 0.0f;

    // ---- prologue: load tile 0 into buffer 0
    {
        const size_t kb = 0;
        cp16(sbase + sA0,          &A4[(size_t)(bm + l_row0) * 192 + kb + l_ch]);
        cp16(sbase + sA1,          &A4[(size_t)(bm + l_row1) * 192 + kb + l_ch]);
        cp16(sbase + TILEB + sA0,  &B4[(size_t)(bn + l_row0) * 192 + kb + l_ch]);
        cp16(sbase + TILEB + sA1,  &B4[(size_t)(bn + l_row1) * 192 + kb + l_ch]);
        cp_commit();
    }

    for (int c = 0; c < NKIT; c++) {
        if (c + 1 < NKIT) {
            const uint32_t nb = ((c + 1) & 1) * BUFB;
            const size_t kb = (size_t)(c + 1) * 4;
            cp16(sbase + nb + sA0,         &A4[(size_t)(bm + l_row0) * 192 + kb + l_ch]);
            cp16(sbase + nb + sA1,         &A4[(size_t)(bm + l_row1) * 192 + kb + l_ch]);
            cp16(sbase + nb + TILEB + sA0, &B4[(size_t)(bn + l_row0) * 192 + kb + l_ch]);
            cp16(sbase + nb + TILEB + sA1, &B4[(size_t)(bn + l_row1) * 192 + kb + l_ch]);
            cp_commit();
            cp_wait<1>();
        } else {
            cp_wait<0>();
        }
        __syncthreads();

        const uint32_t ab = sbase + (c & 1) * BUFB;
        const uint32_t bb = ab + TILEB;
        #pragma unroll
        for (int kk = 0; kk < 2; kk++) {
            uint32_t afr[2][4];
            #pragma unroll
            for (int mt = 0; mt < 2; mt++)
                ldsm4(afr[mt][0], afr[mt][1], afr[mt][2], afr[mt][3],
                      ab + a_off[mt] + kk * 32);
            #pragma unroll
            for (int np = 0; np < 4; np++) {
                uint32_t r0, r1, r2, r3;
                ldsm4(r0, r1, r2, r3, bb + b_off[np] + kk * 32);
                #pragma unroll
                for (int mt = 0; mt < 2; mt++) {
                    mma16816(acc[mt][np * 2],     afr[mt], r0, r1);
                    mma16816(acc[mt][np * 2 + 1], afr[mt], r2, r3);
                }
            }
        }
        __syncthreads();
    }

    // ---- epilogue --------------------------------------------------------
    const int r_in = lane >> 2;          // 0..7
    const int c_in = (lane & 3) * 2;
    #pragma unroll
    for (int mt = 0; mt < 2; mt++) {
        const int m0 = bm + warpM * 32 + mt * 16 + r_in;   // and m0+8
        #pragma unroll
        for (int nt = 0; nt < 8; nt++) {
            const int nb = bn + warpN * 64 + nt * 8 + c_in;
            float v00 = acc[mt][nt][0], v01 = acc[mt][nt][1];
            float v10 = acc[mt][nt][2], v11 = acc[mt][nt][3];
            if (mode == 0) {
                const float bia0 = s_bias[nb - bn], bia1 = s_bias[nb - bn + 1];
                v00 += bia0; v01 += bia1; v10 += bia0; v11 += bia1;
                *(float2*)(g_pre + (size_t)m0 * EDIM + nb)       = make_float2(v00, v01);
                *(float2*)(g_pre + (size_t)(m0 + 8) * EDIM + nb) = make_float2(v10, v11);
                if ((m0 & 7) == 0) {   // rows m0 and m0+8 are both t=0 rows
                    #pragma unroll
                    for (int h = 0; h < 2; h++) {
                        const size_t w = (size_t)(m0 + 8 * h) >> 3;
                        float a0 = tanhf(h ? v10 : v00);
                        float a1 = tanhf(h ? v11 : v01);
                        __nv_bfloat16 x0,x1,y0,y1;
                        split2(a0, x0, y0); split2(a1, x1, y1);
                        __nv_bfloat16* hd = h0_out + w * KSPLIT + nb;
                        *(__nv_bfloat162*)(hd)        = __nv_bfloat162{x0, x1};
                        *(__nv_bfloat162*)(hd + 512)  = __nv_bfloat162{x0, x1};
                        *(__nv_bfloat162*)(hd + 1024) = __nv_bfloat162{y0, y1};
                    }
                }
            } else {
                #pragma unroll
                for (int h = 0; h < 2; h++) {
                    const int m = m0 + 8 * h;
                    float2 pr = *(const float2*)(g_pre + ((size_t)m * TSTEPS + t) * EDIM + nb);
                    float a0 = tanhf((h ? v10 : v00) + pr.x);
                    float a1 = tanhf((h ? v11 : v01) + pr.y);
                    if (t == TSTEPS - 1) {
                        *(float2*)(outp + (size_t)m * EDIM + nb) = make_float2(a0, a1);
                    } else {
                        __nv_bfloat16 x0,x1,y0,y1;
                        split2(a0, x0, y0); split2(a1, x1, y1);
                        __nv_bfloat16* hd = hs_out + (size_t)m * KSPLIT + nb;
                        *(__nv_bfloat162*)(hd)        = __nv_bfloat162{x0, x1};
                        *(__nv_bfloat162*)(hd + 512)  = __nv_bfloat162{x0, x1};
                        *(__nv_bfloat162*)(hd + 1024) = __nv_bfloat162{y0, y1};
                    }
                }
            }
        }
    }
}

// ---------------- host ------------------------------------------------------
extern "C" void kernel_launch(void* const* d_in, const int* in_sizes, int n_in,
                              void* d_out, int out_size)
{
    (void)in_sizes; (void)n_in; (void)out_size;
    const float* x    = (const float*)d_in[0];
    const float* W_ih = (const float*)d_in[1];
    const float* W_hh = (const float*)d_in[2];
    const float* b_ih = (const float*)d_in[3];
    const float* b_hh = (const float*)d_in[4];
    float* out = (float*)d_out;

    static __nv_bfloat16* p_xs = nullptr;
    static __nv_bfloat16* p_ws[2];
    static __nv_bfloat16* p_hs[2];
    if (!p_xs) {
        void* p;
        cudaGetSymbolAddress(&p, g_xs); p_xs = (__nv_bfloat16*)p;
        cudaGetSymbolAddress(&p, g_ws);
        p_ws[0] = (__nv_bfloat16*)p;
        p_ws[1] = p_ws[0] + (size_t)EDIM * KSPLIT;
        cudaGetSymbolAddress(&p, g_hs);
        p_hs[0] = (__nv_bfloat16*)p;
        p_hs[1] = p_hs[0] + (size_t)NWIN * KSPLIT;
    }

    prep_w<<<2048, 256>>>(W_ih, W_hh);
    prep_x<<<32768, 256>>>(x);

    const int smem = 2 * TILEB * 2;   // 40960 B

    // pre = X'' @ Wih''^T + bias ; fused H0 for t=0 rows
    gemm_bf16x3<<<dim3(4, 512), 256, smem>>>(p_xs, p_ws[0], b_ih, b_hh,
                                             nullptr, nullptr, p_hs[0], 0, 0);

    for (int t = 1; t < TSTEPS; t++) {
        gemm_bf16x3<<<dim3(4, 64), 256, smem>>>(
            p_hs[(t - 1) & 1], p_ws[1], nullptr, nullptr,
            (t == TSTEPS - 1) ? out : nullptr, p_hs[t & 1], nullptr, 1, t);
    }
}

// round 4
// speedup vs baseline: 2.3250x; 1.0902x over previous
#include <cuda_runtime.h>
#include <cuda_bf16.h>
#include <cstdint>
#include <math.h>

#define EDIM   512
#define TSTEPS 8
#define NWIN   8192
#define XROWS  65536
#define KSTORE 1024            // A/H stored as [hi(512) | lo(512)]
#define KSPLIT 1536            // logical K'' (3 products); W stored [wh|wl|wh]
#define BK     32              // bf16 K per smem tile
#define NKIT   (KSPLIT / BK)   // 48
#define ROWB   80              // padded smem row stride (64B data + 16B pad)
#define TILEB  (128 * ROWB)    // 10240 B per operand tile
#define STAGEB (2 * TILEB)     // A+B per stage = 20480
#define NSTAGE 4
#define SMEMB  (NSTAGE * STAGEB)   // 81920

// ---------------- scratch (device globals) ----------------------------------
__device__ __nv_bfloat16 g_xs[(size_t)XROWS * KSTORE];      // 134 MB
__device__ __nv_bfloat16 g_ws[2][(size_t)EDIM * KSPLIT];    // 2 x 1.5 MB
__device__ __nv_bfloat16 g_hs[2][(size_t)NWIN * KSTORE];    // 2 x 16.8 MB
__device__ float         g_pre[(size_t)XROWS * EDIM];       // 134 MB

// ---------------- helpers ----------------------------------------------------
__device__ __forceinline__ uint32_t smem_u32(const void* p) {
    uint32_t a;
    asm("{ .reg .u64 t; cvta.to.shared.u64 t, %1; cvt.u32.u64 %0, t; }"
        : "=r"(a) : "l"(p));
    return a;
}
__device__ __forceinline__ void cp16(uint32_t saddr, const void* gaddr) {
    asm volatile("cp.async.cg.shared.global [%0], [%1], 16;"
                 :: "r"(saddr), "l"(gaddr) : "memory");
}
__device__ __forceinline__ void cp_commit() {
    asm volatile("cp.async.commit_group;" ::: "memory");
}
template <int N>
__device__ __forceinline__ void cp_wait() {
    asm volatile("cp.async.wait_group %0;" :: "n"(N) : "memory");
}
__device__ __forceinline__ void ldsm4(uint32_t& r0, uint32_t& r1, uint32_t& r2,
                                      uint32_t& r3, uint32_t addr) {
    asm volatile("ldmatrix.sync.aligned.m8n8.x4.shared.b16 {%0,%1,%2,%3}, [%4];"
                 : "=r"(r0), "=r"(r1), "=r"(r2), "=r"(r3) : "r"(addr));
}
__device__ __forceinline__ void mma16816(float* c, const uint32_t* a,
                                         uint32_t b0, uint32_t b1) {
    asm volatile("mma.sync.aligned.m16n8k16.row.col.f32.bf16.bf16.f32 "
                 "{%0,%1,%2,%3}, {%4,%5,%6,%7}, {%8,%9}, {%0,%1,%2,%3};"
                 : "+f"(c[0]), "+f"(c[1]), "+f"(c[2]), "+f"(c[3])
                 : "r"(a[0]), "r"(a[1]), "r"(a[2]), "r"(a[3]), "r"(b0), "r"(b1));
}
__device__ __forceinline__ void split2(float v, __nv_bfloat16& hi, __nv_bfloat16& lo) {
    hi = __float2bfloat16(v);
    lo = __float2bfloat16(v - __bfloat162float(hi));
}

// ---------------- prep kernels ----------------------------------------------
__global__ __launch_bounds__(256)
void prep_w(const float* __restrict__ wih, const float* __restrict__ whh) {
    int idx = blockIdx.x * 256 + threadIdx.x;           // 0 .. 2*512*512-1
    int which = idx >> 18;
    int e = idx & 262143;
    int n = e >> 9, k = e & 511;
    const float* src = which ? whh : wih;
    __nv_bfloat16 hi, lo;
    split2(src[n * 512 + k], hi, lo);
    __nv_bfloat16* dst = g_ws[which] + (size_t)n * KSPLIT;
    dst[k] = hi; dst[512 + k] = lo; dst[1024 + k] = hi;
}

__global__ __launch_bounds__(256)
void prep_x(const float* __restrict__ x) {
    size_t idx = (size_t)blockIdx.x * 256 + threadIdx.x;  // over 65536*128 float4
    size_t row = idx >> 7;
    int q = (int)(idx & 127);
    float4 v = ((const float4*)x)[idx];
    __nv_bfloat16 h0,h1,h2,h3,l0,l1,l2,l3;
    split2(v.x,h0,l0); split2(v.y,h1,l1); split2(v.z,h2,l2); split2(v.w,h3,l3);
    __nv_bfloat16* base = g_xs + row * KSTORE + q * 4;
    *(__nv_bfloat162*)(base)       = __nv_bfloat162{h0,h1};
    *(__nv_bfloat162*)(base + 2)   = __nv_bfloat162{h2,h3};
    *(__nv_bfloat162*)(base + 512) = __nv_bfloat162{l0,l1};
    *(__nv_bfloat162*)(base + 514) = __nv_bfloat162{l2,l3};
}

// ---------------- bf16x3 HMMA GEMM ------------------------------------------
// C[m][n] = sum over K''=1536 of A''[m][k]*W''[n][k]; A'' chunk c maps to
// stored chunk (c<16 ? c : c-16) of the [hi|lo] layout.
// mode 0: g_pre = acc + bias; t=0 rows also write tanh-split H0
// mode 1: h = tanh(acc + pre_t); split-bf16 h out (fp32 out at t=7)
__global__ __launch_bounds__(256, 2)
void gemm_bf16x3(const __nv_bfloat16* __restrict__ A,
                 const __nv_bfloat16* __restrict__ Bw,
                 const float* __restrict__ b0, const float* __restrict__ b1,
                 float* __restrict__ outp, __nv_bfloat16* __restrict__ hs_out,
                 __nv_bfloat16* __restrict__ h0_out,
                 int mode, int t)
{
    extern __shared__ __align__(16) char dyn[];   // NSTAGE x [A:10240 | B:10240]
    __shared__ float s_bias[128];

    const int tid = threadIdx.x;
    const int wid = tid >> 5;
    const int lane = tid & 31;
    const int warpM = wid & 3;
    const int warpN = wid >> 2;
    const int bm = blockIdx.y * 128;
    const int bn = blockIdx.x * 128;

    const uint32_t sbase = smem_u32(dyn);

    if (mode == 0 && tid < 128) s_bias[tid] = b0[bn + tid] + b1[bn + tid];

    // Loader mapping: 512 16B-chunks per operand tile; thread does 2 A + 2 B.
    const int l_row0 = tid >> 2;            // rows 0..63
    const int l_row1 = l_row0 + 64;
    const int l_ch   = tid & 3;
    const uint4* A4 = (const uint4*)A;      // row stride 128 uint4 (KSTORE)
    const uint4* B4 = (const uint4*)Bw;     // row stride 192 uint4 (KSPLIT)

    const uint32_t sA0 = l_row0 * ROWB + l_ch * 16;
    const uint32_t sA1 = l_row1 * ROWB + l_ch * 16;
    const uint4* Ap0 = &A4[(size_t)(bm + l_row0) * 128 + l_ch];
    const uint4* Ap1 = &A4[(size_t)(bm + l_row1) * 128 + l_ch];
    const uint4* Bp0 = &B4[(size_t)(bn + l_row0) * 192 + l_ch];
    const uint4* Bp1 = &B4[(size_t)(bn + l_row1) * 192 + l_ch];

    // ldmatrix lane offsets (per stage-relative)
    const int g = lane >> 3;
    uint32_t a_off[2], b_off[4];
    #pragma unroll
    for (int mt = 0; mt < 2; mt++)
        a_off[mt] = (uint32_t)((warpM * 32 + mt * 16 + (g & 1) * 8 + (lane & 7)) * ROWB
                               + (g >> 1) * 16);
    #pragma unroll
    for (int np = 0; np < 4; np++)
        b_off[np] = (uint32_t)((warpN * 64 + np * 16 + (g >> 1) * 8 + (lane & 7)) * ROWB
                               + (g & 1) * 16);

    float acc[2][8][4];
    #pragma unroll
    for (int i = 0; i < 2; i++)
        #pragma unroll
        for (int j = 0; j < 8; j++)
            #pragma unroll
            for (int q = 0; q < 4; q++) acc[i][j][q] = 0.0f;

    // ---- prologue: fill stages 0..NSTAGE-2
    #pragma unroll
    for (int s = 0; s < NSTAGE - 1; s++) {
        const uint32_t st = sbase + s * STAGEB;
        const int ka = (s < 16 ? s : s - 16) * 4;
        const int kb = s * 4;
        cp16(st + sA0,         Ap0 + ka);
        cp16(st + sA1,         Ap1 + ka);
        cp16(st + TILEB + sA0, Bp0 + kb);
        cp16(st + TILEB + sA1, Bp1 + kb);
        cp_commit();
    }

    for (int c = 0; c < NKIT; c++) {
        cp_wait<NSTAGE - 2>();
        __syncthreads();

        // issue load for chunk c+NSTAGE-1 into the slot freed by iter c-1
        const int cn = c + NSTAGE - 1;
        if (cn < NKIT) {
            const uint32_t st = sbase + (cn & (NSTAGE - 1)) * STAGEB;
            const int ka = (cn < 16 ? cn : cn - 16) * 4;
            const int kb = cn * 4;
            cp16(st + sA0,         Ap0 + ka);
            cp16(st + sA1,         Ap1 + ka);
            cp16(st + TILEB + sA0, Bp0 + kb);
            cp16(st + TILEB + sA1, Bp1 + kb);
        }
        cp_commit();   // unconditional: keeps group accounting exact at the tail

        const uint32_t ab = sbase + (c & (NSTAGE - 1)) * STAGEB;
        const uint32_t bb = ab + TILEB;
        #pragma unroll
        for (int kk = 0; kk < 2; kk++) {
            uint32_t afr[2][4];
            #pragma unroll
            for (int mt = 0; mt < 2; mt++)
                ldsm4(afr[mt][0], afr[mt][1], afr[mt][2], afr[mt][3],
                      ab + a_off[mt] + kk * 32);
            #pragma unroll
            for (int np = 0; np < 4; np++) {
                uint32_t r0, r1, r2, r3;
                ldsm4(r0, r1, r2, r3, bb + b_off[np] + kk * 32);
                #pragma unroll
                for (int mt = 0; mt < 2; mt++) {
                    mma16816(acc[mt][np * 2],     afr[mt], r0, r1);
                    mma16816(acc[mt][np * 2 + 1], afr[mt], r2, r3);
                }
            }
        }
    }

    // ---- epilogue --------------------------------------------------------
    const int r_in = lane >> 2;
    const int c_in = (lane & 3) * 2;
    #pragma unroll
    for (int mt = 0; mt < 2; mt++) {
        const int m0 = bm + warpM * 32 + mt * 16 + r_in;   // and m0+8
        #pragma unroll
        for (int nt = 0; nt < 8; nt++) {
            const int nb = bn + warpN * 64 + nt * 8 + c_in;
            float v00 = acc[mt][nt][0], v01 = acc[mt][nt][1];
            float v10 = acc[mt][nt][2], v11 = acc[mt][nt][3];
            if (mode == 0) {
                const float bia0 = s_bias[nb - bn], bia1 = s_bias[nb - bn + 1];
                v00 += bia0; v01 += bia1; v10 += bia0; v11 += bia1;
                *(float2*)(g_pre + (size_t)m0 * EDIM + nb)       = make_float2(v00, v01);
                *(float2*)(g_pre + (size_t)(m0 + 8) * EDIM + nb) = make_float2(v10, v11);
                if ((m0 & 7) == 0) {
                    #pragma unroll
                    for (int h = 0; h < 2; h++) {
                        const size_t w = (size_t)(m0 + 8 * h) >> 3;
                        float a0 = tanhf(h ? v10 : v00);
                        float a1 = tanhf(h ? v11 : v01);
                        __nv_bfloat16 x0,x1,y0,y1;
                        split2(a0, x0, y0); split2(a1, x1, y1);
                        __nv_bfloat16* hd = h0_out + w * KSTORE + nb;
                        *(__nv_bfloat162*)(hd)       = __nv_bfloat162{x0, x1};
                        *(__nv_bfloat162*)(hd + 512) = __nv_bfloat162{y0, y1};
                    }
                }
            } else {
                #pragma unroll
                for (int h = 0; h < 2; h++) {
                    const int m = m0 + 8 * h;
                    float2 pr = *(const float2*)(g_pre + ((size_t)m * TSTEPS + t) * EDIM + nb);
                    float a0 = tanhf((h ? v10 : v00) + pr.x);
                    float a1 = tanhf((h ? v11 : v01) + pr.y);
                    if (t == TSTEPS - 1) {
                        *(float2*)(outp + (size_t)m * EDIM + nb) = make_float2(a0, a1);
                    } else {
                        __nv_bfloat16 x0,x1,y0,y1;
                        split2(a0, x0, y0); split2(a1, x1, y1);
                        __nv_bfloat16* hd = hs_out + (size_t)m * KSTORE + nb;
                        *(__nv_bfloat162*)(hd)       = __nv_bfloat162{x0, x1};
                        *(__nv_bfloat162*)(hd + 512) = __nv_bfloat162{y0, y1};
                    }
                }
            }
        }
    }
}

// ---------------- host ------------------------------------------------------
extern "C" void kernel_launch(void* const* d_in, const int* in_sizes, int n_in,
                              void* d_out, int out_size)
{
    (void)in_sizes; (void)n_in; (void)out_size;
    const float* x    = (const float*)d_in[0];
    const float* W_ih = (const float*)d_in[1];
    const float* W_hh = (const float*)d_in[2];
    const float* b_ih = (const float*)d_in[3];
    const float* b_hh = (const float*)d_in[4];
    float* out = (float*)d_out;

    static __nv_bfloat16* p_xs = nullptr;
    static __nv_bfloat16* p_ws[2];
    static __nv_bfloat16* p_hs[2];
    if (!p_xs) {
        void* p;
        cudaGetSymbolAddress(&p, g_xs); p_xs = (__nv_bfloat16*)p;
        cudaGetSymbolAddress(&p, g_ws);
        p_ws[0] = (__nv_bfloat16*)p;
        p_ws[1] = p_ws[0] + (size_t)EDIM * KSPLIT;
        cudaGetSymbolAddress(&p, g_hs);
        p_hs[0] = (__nv_bfloat16*)p;
        p_hs[1] = p_hs[0] + (size_t)NWIN * KSTORE;
        cudaFuncSetAttribute(gemm_bf16x3,
                             cudaFuncAttributeMaxDynamicSharedMemorySize, SMEMB);
    }

    prep_w<<<2048, 256>>>(W_ih, W_hh);
    prep_x<<<32768, 256>>>(x);

    // pre = X'' @ Wih''^T + bias ; fused H0 for t=0 rows
    gemm_bf16x3<<<dim3(4, 512), 256, SMEMB>>>(p_xs, p_ws[0], b_ih, b_hh,
                                              nullptr, nullptr, p_hs[0], 0, 0);

    for (int t = 1; t < TSTEPS; t++) {
        gemm_bf16x3<<<dim3(4, 64), 256, SMEMB>>>(
            p_hs[(t - 1) & 1], p_ws[1], nullptr, nullptr,
            (t == TSTEPS - 1) ? out : nullptr, p_hs[t & 1], nullptr, 1, t);
    }
}